// round 1
// baseline (speedup 1.0000x reference)
#include <cuda_runtime.h>

#define BB 2
#define SS 2048
#define DD 1024
#define HH 16
#define DKH 64
#define BHH (BB*HH)

// Scratch (allocation-free rule: __device__ globals)
__device__ float g_q[BHH * SS * DKH];
__device__ float g_k[BHH * SS * DKH];
__device__ float g_v[BHH * SS * DKH];
__device__ float g_ctx[BB * SS * HH * DKH];

// ---------------------------------------------------------------------------
// Kernel 1: QKV projection.  out[bh][s][k] = X[t] . W[h][:,k] + b[h][k]
// grid: (32 token-tiles of 128, 16 heads, 3 {q,k,v}); block: 256 threads
// Block tile: 128 tokens x 64 (full head dim), BK=16
// ---------------------------------------------------------------------------
__global__ __launch_bounds__(256) void qkv_kernel(
    const float* __restrict__ X,
    const float* __restrict__ Wq, const float* __restrict__ bq,
    const float* __restrict__ Wk, const float* __restrict__ bk,
    const float* __restrict__ Wv, const float* __restrict__ bv)
{
    const int m0 = blockIdx.x * 128;
    const int h  = blockIdx.y;
    const int which = blockIdx.z;

    const float* W; const float* bias; float* out;
    if (which == 0)      { W = Wq; bias = bq; out = g_q; }
    else if (which == 1) { W = Wk; bias = bk; out = g_k; }
    else                 { W = Wv; bias = bv; out = g_v; }
    W    += (size_t)h * DD * DKH;
    bias += h * DKH;

    __shared__ float Xs[128][16];
    __shared__ float Ws[16][64];

    const int tid = threadIdx.x;
    const int ty = tid >> 4;       // 0..15  -> 8 rows each
    const int tx = tid & 15;       // 0..15  -> 4 cols each

    float acc[8][4] = {};

    for (int k0 = 0; k0 < DD; k0 += 16) {
        // X tile: 128x16 = 512 float4, 2 per thread
        #pragma unroll
        for (int l = 0; l < 2; l++) {
            int idx = tid + l * 256;
            int r = idx >> 2, c = idx & 3;
            float4 v = *(const float4*)&X[(size_t)(m0 + r) * DD + k0 + c * 4];
            *(float4*)&Xs[r][c * 4] = v;
        }
        // W tile: 16x64 = 256 float4, 1 per thread
        {
            int r = tid >> 4, c = tid & 15;
            float4 v = *(const float4*)&W[(size_t)(k0 + r) * DKH + c * 4];
            *(float4*)&Ws[r][c * 4] = v;
        }
        __syncthreads();

        #pragma unroll
        for (int kk = 0; kk < 16; kk++) {
            float a[8];
            #pragma unroll
            for (int i = 0; i < 8; i++) a[i] = Xs[ty * 8 + i][kk];
            float4 b = *(float4*)&Ws[kk][tx * 4];
            #pragma unroll
            for (int i = 0; i < 8; i++) {
                acc[i][0] = fmaf(a[i], b.x, acc[i][0]);
                acc[i][1] = fmaf(a[i], b.y, acc[i][1]);
                acc[i][2] = fmaf(a[i], b.z, acc[i][2]);
                acc[i][3] = fmaf(a[i], b.w, acc[i][3]);
            }
        }
        __syncthreads();
    }

    const float4 bb = *(const float4*)&bias[tx * 4];
    #pragma unroll
    for (int i = 0; i < 8; i++) {
        int t  = m0 + ty * 8 + i;
        int b_ = t >> 11;            // /2048
        int s_ = t & (SS - 1);
        float4 o;
        o.x = acc[i][0] + bb.x;
        o.y = acc[i][1] + bb.y;
        o.z = acc[i][2] + bb.z;
        o.w = acc[i][3] + bb.w;
        *(float4*)&out[((size_t)(b_ * HH + h) * SS + s_) * DKH + tx * 4] = o;
    }
}

// ---------------------------------------------------------------------------
// Kernel 2: flash attention per (bh, 128-query tile).
// grid: (16 q-tiles, 32 bh); block 256 threads (16x16).
// smem: Qst[64][136] (transposed, scaled), Kst[64][136], Vs[128][64], Ps[128][128]
// ---------------------------------------------------------------------------
#define ATTN_SMEM_FLOATS (2 * 64 * 136 + 128 * 64 + 128 * 128)
#define ATTN_SMEM_BYTES  (ATTN_SMEM_FLOATS * 4)

__global__ __launch_bounds__(256) void attn_kernel()
{
    extern __shared__ float smem[];
    float (*Qst)[136] = (float(*)[136])(smem);
    float (*Kst)[136] = (float(*)[136])(smem + 64 * 136);
    float (*Vs)[64]   = (float(*)[64]) (smem + 2 * 64 * 136);
    float (*Ps)[128]  = (float(*)[128])(smem + 2 * 64 * 136 + 128 * 64);

    const int bh = blockIdx.y;
    const int q0 = blockIdx.x * 128;
    const float* Q = g_q + (size_t)bh * SS * DKH;
    const float* K = g_k + (size_t)bh * SS * DKH;
    const float* V = g_v + (size_t)bh * SS * DKH;

    const int tid = threadIdx.x;
    const int ty = tid >> 4;
    const int tx = tid & 15;

    // Load + transpose Q tile, pre-scaled by 1/sqrt(64)
    {
        int row  = tid >> 1;        // 0..127
        int half = tid & 1;
        #pragma unroll
        for (int it = 0; it < 8; it++) {
            int c = half * 8 + it;  // float4 col index 0..15
            float4 v = *(const float4*)&Q[(size_t)(q0 + row) * DKH + c * 4];
            Qst[c * 4 + 0][row] = v.x * 0.125f;
            Qst[c * 4 + 1][row] = v.y * 0.125f;
            Qst[c * 4 + 2][row] = v.z * 0.125f;
            Qst[c * 4 + 3][row] = v.w * 0.125f;
        }
    }

    float m[8], l[8], o[8][4];
    #pragma unroll
    for (int i = 0; i < 8; i++) {
        m[i] = -1e30f; l[i] = 0.0f;
        #pragma unroll
        for (int j = 0; j < 4; j++) o[i][j] = 0.0f;
    }

    for (int t = 0; t < SS / 128; t++) {
        __syncthreads();   // previous tile fully consumed (also covers Q stores at t=0)

        // load K tile transposed
        {
            int row = tid >> 1, half = tid & 1;
            #pragma unroll
            for (int it = 0; it < 8; it++) {
                int c = half * 8 + it;
                float4 v = *(const float4*)&K[(size_t)(t * 128 + row) * DKH + c * 4];
                Kst[c * 4 + 0][row] = v.x;
                Kst[c * 4 + 1][row] = v.y;
                Kst[c * 4 + 2][row] = v.z;
                Kst[c * 4 + 3][row] = v.w;
            }
        }
        // load V tile row-major: 2048 float4, 8 per thread
        #pragma unroll
        for (int lq = 0; lq < 8; lq++) {
            int idx = tid + lq * 256;
            int r = idx >> 4, c = idx & 15;
            *(float4*)&Vs[r][c * 4] =
                *(const float4*)&V[(size_t)(t * 128 + r) * DKH + c * 4];
        }
        __syncthreads();

        // S = Q K^T  (128x128 tile, 8x8 per thread)
        float s[8][8] = {};
        #pragma unroll 4
        for (int d = 0; d < 64; d++) {
            float4 a0 = *(float4*)&Qst[d][ty * 8];
            float4 a1 = *(float4*)&Qst[d][ty * 8 + 4];
            float4 b0 = *(float4*)&Kst[d][tx * 8];
            float4 b1 = *(float4*)&Kst[d][tx * 8 + 4];
            float a[8] = {a0.x, a0.y, a0.z, a0.w, a1.x, a1.y, a1.z, a1.w};
            float b[8] = {b0.x, b0.y, b0.z, b0.w, b1.x, b1.y, b1.z, b1.w};
            #pragma unroll
            for (int i = 0; i < 8; i++)
                #pragma unroll
                for (int j = 0; j < 8; j++)
                    s[i][j] = fmaf(a[i], b[j], s[i][j]);
        }

        // online softmax (rows shared by 16 tx-lanes; reduce via shfl within 16)
        #pragma unroll
        for (int i = 0; i < 8; i++) {
            float tm = s[i][0];
            #pragma unroll
            for (int j = 1; j < 8; j++) tm = fmaxf(tm, s[i][j]);
            #pragma unroll
            for (int msk = 1; msk < 16; msk <<= 1)
                tm = fmaxf(tm, __shfl_xor_sync(0xffffffffu, tm, msk));
            float mn = fmaxf(m[i], tm);
            float f  = __expf(m[i] - mn);
            m[i] = mn;
            float rs = 0.0f;
            #pragma unroll
            for (int j = 0; j < 8; j++) {
                s[i][j] = __expf(s[i][j] - mn);
                rs += s[i][j];
            }
            #pragma unroll
            for (int msk = 1; msk < 16; msk <<= 1)
                rs += __shfl_xor_sync(0xffffffffu, rs, msk);
            l[i] = l[i] * f + rs;
            #pragma unroll
            for (int j = 0; j < 4; j++) o[i][j] *= f;
        }

        // stage P in smem for the PV GEMM
        #pragma unroll
        for (int i = 0; i < 8; i++) {
            *(float4*)&Ps[ty * 8 + i][tx * 8]     = make_float4(s[i][0], s[i][1], s[i][2], s[i][3]);
            *(float4*)&Ps[ty * 8 + i][tx * 8 + 4] = make_float4(s[i][4], s[i][5], s[i][6], s[i][7]);
        }
        __syncthreads();

        // O += P V  (128x64, 8x4 per thread)
        #pragma unroll 2
        for (int key = 0; key < 128; key++) {
            float4 b = *(float4*)&Vs[key][tx * 4];
            #pragma unroll
            for (int i = 0; i < 8; i++) {
                float a = Ps[ty * 8 + i][key];
                o[i][0] = fmaf(a, b.x, o[i][0]);
                o[i][1] = fmaf(a, b.y, o[i][1]);
                o[i][2] = fmaf(a, b.z, o[i][2]);
                o[i][3] = fmaf(a, b.w, o[i][3]);
            }
        }
    }

    // epilogue: normalize and write ctx in [B][S][H][DV] layout
    const int b_ = bh / HH;
    const int h_ = bh % HH;
    #pragma unroll
    for (int i = 0; i < 8; i++) {
        float inv = 1.0f / l[i];
        int srow = q0 + ty * 8 + i;
        float4 ov = make_float4(o[i][0] * inv, o[i][1] * inv, o[i][2] * inv, o[i][3] * inv);
        *(float4*)&g_ctx[((size_t)(b_ * SS + srow) * HH + h_) * DKH + tx * 4] = ov;
    }
}

// ---------------------------------------------------------------------------
// Kernel 3: output projection  out[t] = ctx[t] @ Wo + bo
// grid: (32, 8); block 256; 128x128 tiles, 8x8 micro, BK=16
// ---------------------------------------------------------------------------
__global__ __launch_bounds__(256) void out_kernel(
    const float* __restrict__ Wo, const float* __restrict__ bo,
    float* __restrict__ out)
{
    __shared__ float As[128][16];
    __shared__ float Bs[16][128];

    const int m0 = blockIdx.x * 128;
    const int n0 = blockIdx.y * 128;
    const int tid = threadIdx.x;
    const int ty = tid >> 4;
    const int tx = tid & 15;

    float acc[8][8] = {};

    for (int k0 = 0; k0 < HH * DKH; k0 += 16) {
        #pragma unroll
        for (int l = 0; l < 2; l++) {
            int idx = tid + l * 256;
            int r = idx >> 2, c = idx & 3;
            *(float4*)&As[r][c * 4] =
                *(const float4*)&g_ctx[(size_t)(m0 + r) * DD + k0 + c * 4];
        }
        #pragma unroll
        for (int l = 0; l < 2; l++) {
            int idx = tid + l * 256;
            int r = idx >> 5, c = idx & 31;
            *(float4*)&Bs[r][c * 4] =
                *(const float4*)&Wo[(size_t)(k0 + r) * DD + n0 + c * 4];
        }
        __syncthreads();

        #pragma unroll
        for (int kk = 0; kk < 16; kk++) {
            float a[8];
            #pragma unroll
            for (int i = 0; i < 8; i++) a[i] = As[ty * 8 + i][kk];
            float4 b0 = *(float4*)&Bs[kk][tx * 8];
            float4 b1 = *(float4*)&Bs[kk][tx * 8 + 4];
            float b[8] = {b0.x, b0.y, b0.z, b0.w, b1.x, b1.y, b1.z, b1.w};
            #pragma unroll
            for (int i = 0; i < 8; i++)
                #pragma unroll
                for (int j = 0; j < 8; j++)
                    acc[i][j] = fmaf(a[i], b[j], acc[i][j]);
        }
        __syncthreads();
    }

    float4 bb0 = *(const float4*)&bo[n0 + tx * 8];
    float4 bb1 = *(const float4*)&bo[n0 + tx * 8 + 4];
    #pragma unroll
    for (int i = 0; i < 8; i++) {
        int r = m0 + ty * 8 + i;
        float4 o0 = make_float4(acc[i][0] + bb0.x, acc[i][1] + bb0.y,
                                acc[i][2] + bb0.z, acc[i][3] + bb0.w);
        float4 o1 = make_float4(acc[i][4] + bb1.x, acc[i][5] + bb1.y,
                                acc[i][6] + bb1.z, acc[i][7] + bb1.w);
        *(float4*)&out[(size_t)r * DD + n0 + tx * 8]     = o0;
        *(float4*)&out[(size_t)r * DD + n0 + tx * 8 + 4] = o1;
    }
}

// ---------------------------------------------------------------------------
extern "C" void kernel_launch(void* const* d_in, const int* in_sizes, int n_in,
                              void* d_out, int out_size)
{
    const float* X  = (const float*)d_in[0];
    const float* Wq = (const float*)d_in[1];
    const float* bq = (const float*)d_in[2];
    const float* Wk = (const float*)d_in[3];
    const float* bk = (const float*)d_in[4];
    const float* Wv = (const float*)d_in[5];
    const float* bv = (const float*)d_in[6];
    const float* Wo = (const float*)d_in[7];
    const float* bo = (const float*)d_in[8];
    float* out = (float*)d_out;

    // Not a stream op: legal during graph capture, idempotent.
    cudaFuncSetAttribute(attn_kernel,
                         cudaFuncAttributeMaxDynamicSharedMemorySize,
                         ATTN_SMEM_BYTES);

    qkv_kernel<<<dim3(32, 16, 3), 256>>>(X, Wq, bq, Wk, bk, Wv, bv);
    attn_kernel<<<dim3(16, 32), 256, ATTN_SMEM_BYTES>>>();
    out_kernel<<<dim3(32, 8), 256>>>(Wo, bo, out);
}